// round 6
// baseline (speedup 1.0000x reference)
#include <cuda_runtime.h>
#include <cstdint>

#define D_DIM   11008
#define K_DIM   172
#define KPAD    176          // logical K padded to 22 blocks of 8
#define NBLK    22           // k8 blocks
#define BS_PITCH 72          // smem row pitch (bank-verified conflict-free)
#define THREADS 256
#define SMEM_BYTES (KPAD * BS_PITCH * 4)   // 50688

// had_K pre-packed into mma fragment order:
//   block (mw, t, b) -> 32 lanes -> float4 {a0, a1, a2, a3}
//   a0 = hK[i][j], a1 = hK[i+8][j], a2 = hK[i][j+4], a3 = hK[i+8][j+4]
//   i = mw*48 + t*16 + q, j = 8b + p. One coalesced LDG.128 per (t,b) per lane.
__device__ float4 g_hKp[4 * 3 * NBLK * 32];

__global__ void prep_hk(const float* __restrict__ hK) {
    int idx = blockIdx.x * blockDim.x + threadIdx.x;
    if (idx >= 4 * 3 * NBLK * 32) return;
    int lane = idx & 31;
    int b    = (idx >> 5) % NBLK;
    int t    = (idx >> 5) / NBLK % 3;
    int mw   = (idx >> 5) / (NBLK * 3);
    int q = lane >> 2, p = lane & 3;
    int i = mw * 48 + t * 16 + q;
    int j = 8 * b + p;
    float v[4];
    #pragma unroll
    for (int e = 0; e < 4; ++e) {
        int ii = i + (e & 1) * 8;
        int jj = j + (e >> 1) * 4;
        float f = (ii < K_DIM && jj < K_DIM) ? hK[ii * K_DIM + jj] : 0.f;
        uint32_t u;
        asm("cvt.rna.tf32.f32 %0, %1;" : "=r"(u) : "f"(f));
        v[e] = __uint_as_float(u);
    }
    g_hKp[idx] = make_float4(v[0], v[1], v[2], v[3]);
}

__global__ __launch_bounds__(THREADS, 2)
void had_mma_kernel(const float* __restrict__ x,
                    float* __restrict__ out)
{
    extern __shared__ float Bs[];            // [KPAD][BS_PITCH], fragment-permuted tf32
    const int tid  = threadIdx.x;
    const int w    = tid >> 5;
    const int lane = tid & 31;
    const int q    = lane >> 2;              // 0..7
    const int p    = lane & 3;               // 0..3
    const int row  = blockIdx.x;

    // ---------- Phase 1: FWHT-64, V=8 per lane (3 reg stages + 3 shfl stages) ----------
    // lane holds m = g + 8k (k=0..7) of chunk c; g = lane&7, chunk-in-group j = lane>>3.
    // Store layout: col'(m) = 4*(m&7) + ((m>>3)&3) + 36*(m>=32)
    //   -> lane writes two contiguous float4s (k=0..3 at col 4g, k=4..7 at col 4g+36)
    //   -> reader (p,q) gets bf0/bf1 for u=0..3 as single aligned LDS.128.
    {
        const float* xr = x + (size_t)row * D_DIM;
        const int g = lane & 7;
        const int j = lane >> 3;
        const float scale = rsqrtf((float)D_DIM);
        #pragma unroll
        for (int it = 0; it < 6; ++it) {
            const int grp = it * 8 + w;          // 43 chunk-groups of 4 (172 chunks exactly)
            if (grp < 43) {
                const int c = grp * 4 + j;
                const float* xc = xr + c * 64 + g;
                float v[8];
                #pragma unroll
                for (int k = 0; k < 8; ++k) v[k] = xc[8 * k];   // coalesced: 1 wf each
                // register butterfly stages: h = 8, 16, 32  (k-strides 1, 2, 4)
                #pragma unroll
                for (int s = 1; s <= 4; s <<= 1) {
                    #pragma unroll
                    for (int k = 0; k < 8; ++k) {
                        if ((k & s) == 0) {
                            float a = v[k], b2 = v[k + s];
                            v[k] = a + b2; v[k + s] = a - b2;
                        }
                    }
                }
                // shuffle stages: h = 1, 2, 4 (within 8-lane chunk group)
                #pragma unroll
                for (int h = 1; h <= 4; h <<= 1) {
                    #pragma unroll
                    for (int k = 0; k < 8; ++k) {
                        float s = __shfl_xor_sync(0xffffffffu, v[k], h);
                        v[k] = (g & h) ? (s - v[k]) : (v[k] + s);
                    }
                }
                // scale -> tf32 bits -> two STS.128 (conflict-free)
                uint32_t u[8];
                #pragma unroll
                for (int k = 0; k < 8; ++k) {
                    float f = v[k] * scale;
                    asm("cvt.rna.tf32.f32 %0, %1;" : "=r"(u[k]) : "f"(f));
                }
                float* bp = Bs + c * BS_PITCH + 4 * g;
                *(float4*)bp = make_float4(__uint_as_float(u[0]), __uint_as_float(u[1]),
                                           __uint_as_float(u[2]), __uint_as_float(u[3]));
                *(float4*)(bp + 36) = make_float4(__uint_as_float(u[4]), __uint_as_float(u[5]),
                                                  __uint_as_float(u[6]), __uint_as_float(u[7]));
            }
        }
        // zero pad rows 172..175 (read by b=21 fragments)
        for (int i = tid; i < 4 * BS_PITCH; i += THREADS)
            Bs[172 * BS_PITCH + i] = 0.f;
    }
    __syncthreads();

    // ---------- Phase 2: C = hK_pad @ Xf via mma.sync tf32 ----------
    const int mw = w & 3;                    // i0 = mw*48
    const int nw = w >> 2;                   // m0 = nw*32
    const int n0 = nw * 32;

    float acc[3][4][4];
    #pragma unroll
    for (int t = 0; t < 3; ++t)
        #pragma unroll
        for (int u = 0; u < 4; ++u)
            #pragma unroll
            for (int r = 0; r < 4; ++r) acc[t][u][r] = 0.f;

    const float4* Aw = g_hKp + (size_t)(mw * 3) * NBLK * 32 + lane;

    #pragma unroll 2
    for (int b = 0; b < NBLK; ++b) {
        // B fragments: one LDS.128 per k-half (u = .x...w), bank-conflict-free
        const float* bp = Bs + (8 * b + p) * BS_PITCH + 4 * q + 36 * nw;
        float4 B0 = *(const float4*)bp;                       // k = 8b+p
        float4 B1 = *(const float4*)(bp + 4 * BS_PITCH);      // k = 8b+p+4
        const uint32_t bf0[4] = { __float_as_uint(B0.x), __float_as_uint(B0.y),
                                  __float_as_uint(B0.z), __float_as_uint(B0.w) };
        const uint32_t bf1[4] = { __float_as_uint(B1.x), __float_as_uint(B1.y),
                                  __float_as_uint(B1.z), __float_as_uint(B1.w) };
        #pragma unroll
        for (int t = 0; t < 3; ++t) {
            float4 a = Aw[(size_t)(t * NBLK + b) * 32];       // one coalesced LDG.128
            const uint32_t a0 = __float_as_uint(a.x), a1 = __float_as_uint(a.y);
            const uint32_t a2 = __float_as_uint(a.z), a3 = __float_as_uint(a.w);
            #pragma unroll
            for (int u = 0; u < 4; ++u) {
                asm volatile(
                    "mma.sync.aligned.m16n8k8.row.col.f32.tf32.tf32.f32 "
                    "{%0,%1,%2,%3}, {%4,%5,%6,%7}, {%8,%9}, {%0,%1,%2,%3};"
                    : "+f"(acc[t][u][0]), "+f"(acc[t][u][1]),
                      "+f"(acc[t][u][2]), "+f"(acc[t][u][3])
                    : "r"(a0), "r"(a1), "r"(a2), "r"(a3),
                      "r"(bf0[u]), "r"(bf1[u]));
            }
        }
    }

    // ---------- Phase 3: direct coalesced-enough store (8 rows x 32B runs = 2 wf/STG) ----------
    {
        float* orow = out + (size_t)row * D_DIM;
        const int i0 = mw * 48;
        #pragma unroll
        for (int t = 0; t < 3; ++t) {
            const int ib = i0 + t * 16 + q;
            #pragma unroll
            for (int u = 0; u < 4; ++u) {
                const int m = n0 + u * 8 + 2 * p;
                if (ib < K_DIM)
                    *(float2*)(orow + ib * 64 + m) = make_float2(acc[t][u][0], acc[t][u][1]);
                if (ib + 8 < K_DIM)
                    *(float2*)(orow + (ib + 8) * 64 + m) = make_float2(acc[t][u][2], acc[t][u][3]);
            }
        }
    }
}

extern "C" void kernel_launch(void* const* d_in, const int* in_sizes, int n_in,
                              void* d_out, int out_size)
{
    const float* x  = (const float*)d_in[0];
    const float* hK = (const float*)d_in[1];
    int nx = in_sizes[0];
    if (n_in > 1 && in_sizes[0] == K_DIM * K_DIM) {   // defensive input-order check
        x  = (const float*)d_in[1];
        hK = (const float*)d_in[0];
        nx = in_sizes[1];
    }
    float* out = (float*)d_out;
    const int nrows = nx / D_DIM;

    cudaFuncSetAttribute(had_mma_kernel,
                         cudaFuncAttributeMaxDynamicSharedMemorySize, SMEM_BYTES);

    prep_hk<<<(4 * 3 * NBLK * 32 + 255) / 256, 256>>>(hK);
    had_mma_kernel<<<nrows, THREADS, SMEM_BYTES>>>(x, out);
}

// round 7
// speedup vs baseline: 1.2343x; 1.2343x over previous
#include <cuda_runtime.h>
#include <cstdint>

#define D_DIM   11008
#define K_DIM   172
#define KPAD    176          // logical K padded to 22 blocks of 8
#define NBLK    22           // k8 blocks
#define BS_PITCH 72          // smem row pitch (bank-verified conflict-free)
#define THREADS 128
#define SMEM_BYTES (KPAD * BS_PITCH * 4)   // 50688

// had_K pre-packed into mma fragment order (unchanged from R5):
//   block (mw, t, b) -> 32 lanes -> float4 {a0, a1, a2, a3}
//   a0 = hK[i][j], a1 = hK[i+8][j], a2 = hK[i][j+4], a3 = hK[i+8][j+4]
//   i = mw*48 + t*16 + q, j = 8b + p. One coalesced LDG.128 per (t,b) per lane.
__device__ float4 g_hKp[4 * 3 * NBLK * 32];

__global__ void prep_hk(const float* __restrict__ hK) {
    int idx = blockIdx.x * blockDim.x + threadIdx.x;
    if (idx >= 4 * 3 * NBLK * 32) return;
    int lane = idx & 31;
    int b    = (idx >> 5) % NBLK;
    int t    = (idx >> 5) / NBLK % 3;
    int mw   = (idx >> 5) / (NBLK * 3);
    int q = lane >> 2, p = lane & 3;
    int i = mw * 48 + t * 16 + q;
    int j = 8 * b + p;
    float v[4];
    #pragma unroll
    for (int e = 0; e < 4; ++e) {
        int ii = i + (e & 1) * 8;
        int jj = j + (e >> 1) * 4;
        float f = (ii < K_DIM && jj < K_DIM) ? hK[ii * K_DIM + jj] : 0.f;
        uint32_t u;
        asm("cvt.rna.tf32.f32 %0, %1;" : "=r"(u) : "f"(f));
        v[e] = __uint_as_float(u);
    }
    g_hKp[idx] = make_float4(v[0], v[1], v[2], v[3]);
}

__global__ __launch_bounds__(THREADS, 3)
void had_mma_kernel(const float* __restrict__ x,
                    float* __restrict__ out)
{
    extern __shared__ float Bs[];            // [KPAD][BS_PITCH] tf32 bits (plain layout)
    const int tid  = threadIdx.x;
    const int w    = tid >> 5;               // 0..3
    const int lane = tid & 31;
    const int q    = lane >> 2;              // 0..7
    const int p    = lane & 3;               // 0..3
    const int row  = blockIdx.x;

    // ---------- Phase 1: FWHT-64 per chunk (R5-style, 4 warps x 44 padded chunks) ----------
    // chunk c = w + 4k, k = 0..43; k=43 -> c in 172..175 computes zeros (pad rows).
    {
        const float* xr = x + (size_t)row * D_DIM;
        const float scale = rsqrtf((float)D_DIM);
        float cur0[4], cur1[4], nxt0[4], nxt1[4];
        #pragma unroll
        for (int e = 0; e < 4; ++e) {        // k = 0..3 always valid
            const int c = w + 4 * e;
            cur0[e] = xr[c * 64 + lane];
            cur1[e] = xr[c * 64 + 32 + lane];
        }
        #pragma unroll
        for (int kb = 0; kb < 44; kb += 4) {
            if (kb + 4 < 44) {
                #pragma unroll
                for (int e = 0; e < 4; ++e) {
                    const int k = kb + 4 + e;
                    const int c = w + 4 * k;
                    if (c < K_DIM) { nxt0[e] = xr[c * 64 + lane]; nxt1[e] = xr[c * 64 + 32 + lane]; }
                    else           { nxt0[e] = 0.f;               nxt1[e] = 0.f; }
                }
            }
            #pragma unroll
            for (int e = 0; e < 4; ++e) {
                const int c = w + 4 * (kb + e);      // < KPAD always
                float t0 = cur0[e] + cur1[e], t1 = cur0[e] - cur1[e];   // stage h=32
                #pragma unroll
                for (int h = 1; h <= 16; h <<= 1) {                     // h=1..16 via shfl
                    float s0 = __shfl_xor_sync(0xffffffffu, t0, h);
                    float s1 = __shfl_xor_sync(0xffffffffu, t1, h);
                    if (lane & h) { t0 = s0 - t0; t1 = s1 - t1; }
                    else          { t0 = t0 + s0; t1 = t1 + s1; }
                }
                t0 *= scale; t1 *= scale;
                uint32_t u0, u1;
                asm("cvt.rna.tf32.f32 %0, %1;" : "=r"(u0) : "f"(t0));
                asm("cvt.rna.tf32.f32 %0, %1;" : "=r"(u1) : "f"(t1));
                Bs[c * BS_PITCH + lane]      = __uint_as_float(u0);  // m = lane
                Bs[c * BS_PITCH + 32 + lane] = __uint_as_float(u1);  // m = lane+32
            }
            #pragma unroll
            for (int e = 0; e < 4; ++e) { cur0[e] = nxt0[e]; cur1[e] = nxt1[e]; }
        }
    }
    __syncthreads();

    // ---------- Phase 2: C = hK_pad @ Xf, warp grid 4M x 1N (u = 0..7 covers all 64 cols) ----------
    const int mw = w;                        // i0 = mw*48

    float acc[3][8][4];
    #pragma unroll
    for (int t = 0; t < 3; ++t)
        #pragma unroll
        for (int u = 0; u < 8; ++u)
            #pragma unroll
            for (int r = 0; r < 4; ++r) acc[t][u][r] = 0.f;

    const float4* Aw = g_hKp + (size_t)(mw * 3) * NBLK * 32 + lane;

    #pragma unroll 2
    for (int b = 0; b < NBLK; ++b) {
        // B fragments: scalar LDS, bank-conflict-free (8p + q + 8u covers all banks)
        uint32_t bf0[8], bf1[8];
        const float* br0 = Bs + (8 * b + p) * BS_PITCH + q;
        const float* br1 = br0 + 4 * BS_PITCH;
        #pragma unroll
        for (int u = 0; u < 8; ++u) {
            bf0[u] = __float_as_uint(br0[u * 8]);
            bf1[u] = __float_as_uint(br1[u * 8]);
        }
        #pragma unroll
        for (int t = 0; t < 3; ++t) {
            float4 a = Aw[(size_t)(t * NBLK + b) * 32];     // one coalesced LDG.128
            const uint32_t a0 = __float_as_uint(a.x), a1 = __float_as_uint(a.y);
            const uint32_t a2 = __float_as_uint(a.z), a3 = __float_as_uint(a.w);
            #pragma unroll
            for (int u = 0; u < 8; ++u) {
                asm volatile(
                    "mma.sync.aligned.m16n8k8.row.col.f32.tf32.tf32.f32 "
                    "{%0,%1,%2,%3}, {%4,%5,%6,%7}, {%8,%9}, {%0,%1,%2,%3};"
                    : "+f"(acc[t][u][0]), "+f"(acc[t][u][1]),
                      "+f"(acc[t][u][2]), "+f"(acc[t][u][3])
                    : "r"(a0), "r"(a1), "r"(a2), "r"(a3),
                      "r"(bf0[u]), "r"(bf1[u]));
            }
        }
    }
    __syncthreads();   // all warps done reading Bs; reuse as output stage

    // ---------- Phase 3: stage accumulators -> coalesced store (R5-proven) ----------
    {
        const int i0 = mw * 48;
        #pragma unroll
        for (int t = 0; t < 3; ++t) {
            const int ib = i0 + t * 16 + q;
            #pragma unroll
            for (int u = 0; u < 8; ++u) {
                const int m = u * 8 + 2 * p;
                if (ib < K_DIM)
                    *(float2*)(Bs + ib * BS_PITCH + m) =
                        make_float2(acc[t][u][0], acc[t][u][1]);
                if (ib + 8 < K_DIM)
                    *(float2*)(Bs + (ib + 8) * BS_PITCH + m) =
                        make_float2(acc[t][u][2], acc[t][u][3]);
            }
        }
    }
    __syncthreads();
    {
        float4* orow4 = (float4*)(out + (size_t)row * D_DIM);
        // 172*64 floats = 2752 float4; conflict-free LDS.128 + coalesced STG.128
        for (int u4 = tid; u4 < (K_DIM * 64) / 4; u4 += THREADS) {
            const int i  = u4 >> 4;
            const int m4 = u4 & 15;
            orow4[u4] = *(const float4*)(Bs + i * BS_PITCH + m4 * 4);
        }
    }
}

extern "C" void kernel_launch(void* const* d_in, const int* in_sizes, int n_in,
                              void* d_out, int out_size)
{
    const float* x  = (const float*)d_in[0];
    const float* hK = (const float*)d_in[1];
    int nx = in_sizes[0];
    if (n_in > 1 && in_sizes[0] == K_DIM * K_DIM) {   // defensive input-order check
        x  = (const float*)d_in[1];
        hK = (const float*)d_in[0];
        nx = in_sizes[1];
    }
    float* out = (float*)d_out;
    const int nrows = nx / D_DIM;

    cudaFuncSetAttribute(had_mma_kernel,
                         cudaFuncAttributeMaxDynamicSharedMemorySize, SMEM_BYTES);

    prep_hk<<<(4 * 3 * NBLK * 32 + 255) / 256, 256>>>(hK);
    had_mma_kernel<<<nrows, THREADS, SMEM_BYTES>>>(x, out);
}

// round 9
// speedup vs baseline: 1.5954x; 1.2926x over previous
#include <cuda_runtime.h>
#include <cuda_fp16.h>
#include <cstdint>
#include <cstring>

#define D_DIM   11008
#define K_DIM   172
#define NKB     11           // k16 blocks (covers j 0..175)
#define NPAIR   88           // chunk pairs (86 real + 2 pad)
#define BP      72           // Bs row pitch in floats (288B) — bank-verified
#define THREADS 128
#define SMEM_BYTES (K_DIM * BP * 4)   // 49536: epilogue staging (Bs half2 area = 25344 fits inside)

static __device__ __forceinline__ uint32_t h2_bits(__half2 h) {
    uint32_t u;
    memcpy(&u, &h, 4);
    return u;
}

// had_K pre-packed into fp16 m16n8k16 A-fragment order:
//   block (mw, t, kb) -> 32 lanes -> uint4 {a0, a1, a2, a3} (each a half2)
//   a0 = {hK[i][k0], hK[i][k0+1]}        a1 = {hK[i+8][k0],   hK[i+8][k0+1]}
//   a2 = {hK[i][k0+8], hK[i][k0+9]}      a3 = {hK[i+8][k0+8], hK[i+8][k0+9]}
//   i = mw*48 + t*16 + q, k0 = 16*kb + 2p.  One coalesced LDG.128 per (t,kb).
__device__ uint4 g_hKh[4 * 3 * NKB * 32];

__global__ void prep_hk(const float* __restrict__ hK) {
    int idx = blockIdx.x * blockDim.x + threadIdx.x;
    if (idx >= 4 * 3 * NKB * 32) return;
    int lane = idx & 31;
    int kb   = (idx >> 5) % NKB;
    int t    = (idx >> 5) / NKB % 3;
    int mw   = (idx >> 5) / (NKB * 3);
    int q = lane >> 2, p = lane & 3;
    int i  = mw * 48 + t * 16 + q;
    int k0 = 16 * kb + 2 * p;
    float f[8];
    #pragma unroll
    for (int e = 0; e < 8; ++e) {
        int ii = i + ((e >> 1) & 1) * 8;          // e: (k-half, row-half, k-lo/hi)
        int kk = k0 + (e >> 2) * 8 + (e & 1);
        f[e] = (ii < K_DIM && kk < K_DIM) ? hK[ii * K_DIM + kk] : 0.f;
    }
    uint4 r;
    r.x = h2_bits(__floats2half2_rn(f[0], f[1]));   // a0
    r.y = h2_bits(__floats2half2_rn(f[2], f[3]));   // a1
    r.z = h2_bits(__floats2half2_rn(f[4], f[5]));   // a2
    r.w = h2_bits(__floats2half2_rn(f[6], f[7]));   // a3
    g_hKh[idx] = r;
}

__global__ __launch_bounds__(THREADS, 3)
void had_mma_kernel(const float* __restrict__ x,
                    float* __restrict__ out)
{
    extern __shared__ float Bs[];   // phase1/2: [NPAIR][BP] half2-in-float; epilogue: [172][BP] f32
    const int tid  = threadIdx.x;
    const int w    = tid >> 5;               // 0..3
    const int lane = tid & 31;
    const int q    = lane >> 2;              // 0..7
    const int p    = lane & 3;               // 0..3
    const int row  = blockIdx.x;

    // ---------- Phase 1: FWHT-64 on chunk PAIRS -> half2-packed Bs ----------
    // pair c2 = w + 4*k2 (k2 = 0..21); chunks 2*c2, 2*c2+1; c2 >= 86 -> zero pad.
    {
        const float* xr = x + (size_t)row * D_DIM;
        const float scale = rsqrtf((float)D_DIM);
        uint32_t* bp32 = (uint32_t*)Bs;
        float cur[4], nxt[4];
        {
            const float* b0 = xr + (size_t)w * 128 + lane;
            cur[0] = b0[0]; cur[1] = b0[32]; cur[2] = b0[64]; cur[3] = b0[96];
        }
        #pragma unroll
        for (int k2 = 0; k2 < 22; ++k2) {
            const int c2 = w + 4 * k2;
            if (k2 + 1 < 22) {
                const int c2n = c2 + 4;
                if (c2n < 86) {
                    const float* bn = xr + (size_t)c2n * 128 + lane;
                    nxt[0] = bn[0]; nxt[1] = bn[32]; nxt[2] = bn[64]; nxt[3] = bn[96];
                } else {
                    nxt[0] = nxt[1] = nxt[2] = nxt[3] = 0.f;
                }
            }
            // FWHT both chunks: E = cur[0..1], O = cur[2..3]
            float e0 = cur[0] + cur[1], e1 = cur[0] - cur[1];   // stage h=32
            float o0 = cur[2] + cur[3], o1 = cur[2] - cur[3];
            #pragma unroll
            for (int h = 1; h <= 16; h <<= 1) {                 // h=1..16 via shfl
                float se0 = __shfl_xor_sync(0xffffffffu, e0, h);
                float se1 = __shfl_xor_sync(0xffffffffu, e1, h);
                float so0 = __shfl_xor_sync(0xffffffffu, o0, h);
                float so1 = __shfl_xor_sync(0xffffffffu, o1, h);
                if (lane & h) { e0 = se0 - e0; e1 = se1 - e1; o0 = so0 - o0; o1 = so1 - o1; }
                else          { e0 = e0 + se0; e1 = e1 + se1; o0 = o0 + so0; o1 = o1 + so1; }
            }
            // pack {even, odd} per m; store rows m=lane, m=lane+32 of pair-row c2
            uint32_t h2a = h2_bits(__floats2half2_rn(e0 * scale, o0 * scale));
            uint32_t h2b = h2_bits(__floats2half2_rn(e1 * scale, o1 * scale));
            bp32[c2 * BP + lane]      = h2a;   // conflict-free: bank = lane + 8c2
            bp32[c2 * BP + lane + 32] = h2b;
            cur[0] = nxt[0]; cur[1] = nxt[1]; cur[2] = nxt[2]; cur[3] = nxt[3];
        }
    }
    __syncthreads();

    // ---------- Phase 2: C = hK @ Xf via mma.sync m16n8k16 fp16 ----------
    const int mw = w;                        // i0 = mw*48; each warp covers all 64 cols

    float acc[3][8][4];
    #pragma unroll
    for (int t = 0; t < 3; ++t)
        #pragma unroll
        for (int u = 0; u < 8; ++u)
            #pragma unroll
            for (int r = 0; r < 4; ++r) acc[t][u][r] = 0.f;

    const uint4* Aw = g_hKh + (size_t)(mw * 3) * NKB * 32 + lane;
    const uint32_t* bq = (const uint32_t*)Bs;

    #pragma unroll 2
    for (int kb = 0; kb < NKB; ++kb) {
        // B fragments: one LDS.32 each, conflict-free (bank = 8(p+u)+q mod 32)
        uint32_t b0[8], b1[8];
        const uint32_t* br = bq + (8 * kb + p) * BP + q;
        #pragma unroll
        for (int u = 0; u < 8; ++u) {
            b0[u] = br[8 * u];                // k-pair row 8kb+p   (k = 16kb+2p, +1)
            b1[u] = br[8 * u + 4 * BP];       // k-pair row 8kb+p+4 (k = 16kb+2p+8, +9)
        }
        #pragma unroll
        for (int t = 0; t < 3; ++t) {
            uint4 a = Aw[(size_t)(t * NKB + kb) * 32];   // one coalesced LDG.128
            #pragma unroll
            for (int u = 0; u < 8; ++u) {
                asm volatile(
                    "mma.sync.aligned.m16n8k16.row.col.f32.f16.f16.f32 "
                    "{%0,%1,%2,%3}, {%4,%5,%6,%7}, {%8,%9}, {%0,%1,%2,%3};"
                    : "+f"(acc[t][u][0]), "+f"(acc[t][u][1]),
                      "+f"(acc[t][u][2]), "+f"(acc[t][u][3])
                    : "r"(a.x), "r"(a.y), "r"(a.z), "r"(a.w),
                      "r"(b0[u]), "r"(b1[u]));
            }
        }
    }
    __syncthreads();   // all warps done reading Bs; reuse as f32 output stage

    // ---------- Phase 3: stage accumulators -> coalesced store ----------
    {
        const int i0 = mw * 48;
        #pragma unroll
        for (int t = 0; t < 3; ++t) {
            const int ib = i0 + t * 16 + q;
            #pragma unroll
            for (int u = 0; u < 8; ++u) {
                const int m = u * 8 + 2 * p;
                if (ib < K_DIM)
                    *(float2*)(Bs + ib * BP + m) =
                        make_float2(acc[t][u][0], acc[t][u][1]);
                if (ib + 8 < K_DIM)
                    *(float2*)(Bs + (ib + 8) * BP + m) =
                        make_float2(acc[t][u][2], acc[t][u][3]);
            }
        }
    }
    __syncthreads();
    {
        float4* orow4 = (float4*)(out + (size_t)row * D_DIM);
        // 172*64 floats = 2752 float4; conflict-free LDS.128 + coalesced STG.128
        for (int u4 = tid; u4 < (K_DIM * 64) / 4; u4 += THREADS) {
            const int i  = u4 >> 4;
            const int m4 = u4 & 15;
            orow4[u4] = *(const float4*)(Bs + i * BP + m4 * 4);
        }
    }
}

extern "C" void kernel_launch(void* const* d_in, const int* in_sizes, int n_in,
                              void* d_out, int out_size)
{
    const float* x  = (const float*)d_in[0];
    const float* hK = (const float*)d_in[1];
    int nx = in_sizes[0];
    if (n_in > 1 && in_sizes[0] == K_DIM * K_DIM) {   // defensive input-order check
        x  = (const float*)d_in[1];
        hK = (const float*)d_in[0];
        nx = in_sizes[1];
    }
    float* out = (float*)d_out;
    const int nrows = nx / D_DIM;

    cudaFuncSetAttribute(had_mma_kernel,
                         cudaFuncAttributeMaxDynamicSharedMemorySize, SMEM_BYTES);

    prep_hk<<<(4 * 3 * NKB * 32 + 255) / 256, 256>>>(hK);
    had_mma_kernel<<<nrows, THREADS, SMEM_BYTES>>>(x, out);
}